// round 14
// baseline (speedup 1.0000x reference)
#include <cuda_runtime.h>
#include <cuda_fp16.h>
#include <cstdint>

// ScaledDotProductAttention B=4,H=16,S=2048,D=64 fp32 + mask [B,1,S,S] int32.
// out [B,H,S,D] then weights [B,H,S,S] concatenated in d_out.
//
// Round 13:
//   k0a (cvt_kv):   K,V f32 -> fp16 scratch.
//   k0b (cvt_mask): mask int32 -> fp16 {0,1} scratch.
//   k1  (sdpa_fused): cp.async double-buffered fp16 K/V; QK=Qh*Kh HMMA with
//        log2e folded into Q scale; e = ex2.approx(s) -> pack -> HMUL2 mask
//        -> g_e (fp16) + PV A-frags; PV=Ph*Vh -> RAW O. No rowsums.
//   k2  (sdpa_norm): warp-per-row: e kept in regs, warp-shuffle rowsum,
//        W = e*rinv (f32), O row normalized. No smem, no bar.sync.

#define B_ 4
#define H_ 16
#define S_ 2048
#define D_ 64

constexpr int BM = 128, BN = 128, NT = 256, NTILE = S_ / BN;
constexpr int RB = 144;                    // bytes per fp16 smem row (72 elems)

// double-buffered tile areas
constexpr int OFF_K0  = 0;
constexpr int OFF_V0  = 18432;
constexpr int OFF_K1  = 36864;
constexpr int OFF_V1  = 55296;
constexpr int SMEM_SZ = 73728;

__device__ __align__(16) __half g_Kh[(size_t)B_ * H_ * S_ * D_];
__device__ __align__(16) __half g_Vh[(size_t)B_ * H_ * S_ * D_];
__device__ __align__(16) __half g_Mh[(size_t)B_ * S_ * S_];        // fp16 {0,1}
__device__ __align__(16) __half g_e[(size_t)B_ * H_ * S_ * S_];    // 536 MB scratch

// ---------- helpers ----------
__device__ __forceinline__ uint32_t smem_u32(const void* p) {
    uint32_t a;
    asm("{ .reg .u64 t; cvta.to.shared.u64 t, %1; cvt.u32.u64 %0, t; }" : "=r"(a) : "l"(p));
    return a;
}
__device__ __forceinline__ void ldsm4(uint32_t* r, uint32_t a) {
    asm volatile("ldmatrix.sync.aligned.m8n8.x4.shared.b16 {%0,%1,%2,%3}, [%4];"
                 : "=r"(r[0]), "=r"(r[1]), "=r"(r[2]), "=r"(r[3]) : "r"(a));
}
__device__ __forceinline__ void ldsm4t(uint32_t* r, uint32_t a) {
    asm volatile("ldmatrix.sync.aligned.m8n8.x4.trans.shared.b16 {%0,%1,%2,%3}, [%4];"
                 : "=r"(r[0]), "=r"(r[1]), "=r"(r[2]), "=r"(r[3]) : "r"(a));
}
__device__ __forceinline__ void mma_f16(float* c, const uint32_t* a, uint32_t b0, uint32_t b1) {
    asm volatile(
        "mma.sync.aligned.m16n8k16.row.col.f32.f16.f16.f32 "
        "{%0,%1,%2,%3}, {%4,%5,%6,%7}, {%8,%9}, {%0,%1,%2,%3};"
        : "+f"(c[0]), "+f"(c[1]), "+f"(c[2]), "+f"(c[3])
        : "r"(a[0]), "r"(a[1]), "r"(a[2]), "r"(a[3]), "r"(b0), "r"(b1));
}
__device__ __forceinline__ uint32_t pack_h2(float a, float b) {
    __half2 h = __floats2half2_rn(a, b);
    return *(uint32_t*)&h;
}
__device__ __forceinline__ uint32_t mul2(uint32_t a, uint32_t b) {
    __half2 r = __hmul2(*(__half2*)&a, *(__half2*)&b);
    return *(uint32_t*)&r;
}
__device__ __forceinline__ float ex2f(float x) {
    float r; asm("ex2.approx.f32 %0, %1;" : "=f"(r) : "f"(x)); return r;
}
__device__ __forceinline__ void cp16(uint32_t dst, const void* src) {
    asm volatile("cp.async.cg.shared.global [%0], [%1], 16;" :: "r"(dst), "l"(src));
}
#define CP_COMMIT() asm volatile("cp.async.commit_group;" ::: "memory")
#define CP_WAIT0()  asm volatile("cp.async.wait_group 0;" ::: "memory")

// ---------- k0a: K,V f32 -> fp16 scratch ----------
__global__ void __launch_bounds__(256, 8)
cvt_kv(const float* __restrict__ K, const float* __restrict__ V)
{
    int i = blockIdx.x * 256 + threadIdx.x;       // 0 .. B*H*S*D/4-1
    float4 a = ((const float4*)K)[i];
    ((uint2*)g_Kh)[i] = make_uint2(pack_h2(a.x, a.y), pack_h2(a.z, a.w));
    float4 b = ((const float4*)V)[i];
    ((uint2*)g_Vh)[i] = make_uint2(pack_h2(b.x, b.y), pack_h2(b.z, b.w));
}

// ---------- k0b: mask int32 -> fp16 {0,1} ----------
__global__ void __launch_bounds__(256, 8)
cvt_mask(const int* __restrict__ mask)
{
    int i = blockIdx.x * 256 + threadIdx.x;       // 0 .. B*S*S/4-1
    int4 m = ((const int4*)mask)[i];
    ((uint2*)g_Mh)[i] = make_uint2(pack_h2((float)m.x, (float)m.y),
                                   pack_h2((float)m.z, (float)m.w));
}

// ---------- k1: QK+ex2+mask -> e(fp16) to g_e, PV -> raw O ----------
__global__ void __launch_bounds__(NT, 2)
sdpa_fused(const float* __restrict__ Q, float* __restrict__ out)
{
    extern __shared__ char sm[];
    const uint32_t sb = smem_u32(sm);
    const int tid = threadIdx.x, w = tid >> 5, lid = tid & 31;
    const int g = lid >> 2, tl = lid & 3, mi = lid >> 3, l7 = lid & 7;
    const int bh = blockIdx.y, b = bh >> 4, q0 = blockIdx.x * BM;

    const float* Qg  = Q + ((size_t)bh * S_ + q0) * D_;
    const char*  KgH = (const char*)(g_Kh + (size_t)bh * S_ * D_);
    const char*  VgH = (const char*)(g_Vh + (size_t)bh * S_ * D_);
    const __half* Mh = g_Mh + (size_t)b * S_ * S_;
    float*       Og  = out + ((size_t)bh * S_ + q0) * D_;
    __half*      Eg  = g_e + ((size_t)bh * S_ + q0) * S_;

    // prologue: Q * (0.125*log2e) fp16 -> smem buf K0, hoist Q frags to regs
    const float QS = 0.125f * 1.44269504f;
    for (int idx = tid; idx < BM * 16; idx += NT) {
        int r = idx >> 4, c4 = (idx & 15) * 4;
        float4 v = *(const float4*)(Qg + (size_t)r * D_ + c4);
        *(uint2*)(sm + OFF_K0 + r * RB + c4 * 2) =
            make_uint2(pack_h2(v.x * QS, v.y * QS),
                       pack_h2(v.z * QS, v.w * QS));
    }
    __syncthreads();

    uint32_t aQH[4][4];
    {
        uint32_t arow = (uint32_t)(16 * w + ((mi & 1) << 3) + l7) * RB;
        #pragma unroll
        for (int kc = 0; kc < 4; ++kc)
            ldsm4(aQH[kc], sb + OFF_K0 + arow + kc * 32 + (mi >> 1) * 16);
    }
    __syncthreads();   // Q frags read before cp.async overwrites K0

    const uint32_t offK[2] = {sb + OFF_K0, sb + OFF_K1};
    const uint32_t offV[2] = {sb + OFF_V0, sb + OFF_V1};

    // issue tile 0
    {
        #pragma unroll
        for (int j = 0; j < 4; ++j) {
            int c = tid + 256 * j, row = c >> 3, cc = c & 7;
            cp16(offK[0] + row * RB + cc * 16, KgH + row * 128 + cc * 16);
            cp16(offV[0] + row * RB + cc * 16, VgH + row * 128 + cc * 16);
        }
        CP_COMMIT();
    }

    const int r0 = 16 * w + g;
    const __half* m0p = Mh + (size_t)(q0 + r0) * S_;
    const __half* m1p = Mh + (size_t)(q0 + r0 + 8) * S_;
    __half* e0p = Eg + (size_t)r0 * S_;
    __half* e1p = Eg + (size_t)(r0 + 8) * S_;

    float o[8][4];
    #pragma unroll
    for (int df = 0; df < 8; ++df)
        #pragma unroll
        for (int i = 0; i < 4; ++i) o[df][i] = 0.f;

    for (int t = 0; t < NTILE; ++t) {
        CP_WAIT0();
        __syncthreads();    // tile t ready; prev compute done (buffer reuse safe)

        if (t + 1 < NTILE) {
            const char* ks = KgH + (size_t)(t + 1) * BN * D_ * 2;
            const char* vs = VgH + (size_t)(t + 1) * BN * D_ * 2;
            const uint32_t dK = offK[(t + 1) & 1], dV = offV[(t + 1) & 1];
            #pragma unroll
            for (int j = 0; j < 4; ++j) {
                int c = tid + 256 * j, row = c >> 3, cc = c & 7;
                cp16(dK + row * RB + cc * 16, ks + row * 128 + cc * 16);
                cp16(dV + row * RB + cc * 16, vs + row * 128 + cc * 16);
            }
            CP_COMMIT();
        }

        const uint32_t bK = offK[t & 1], bV = offV[t & 1];

        #pragma unroll
        for (int ch2 = 0; ch2 < 2; ++ch2) {
            const int co = 64 * ch2;
            const int colb = t * BN + co;

            // hoist mask loads (fp16 pairs): in flight during QK MMAs
            uint32_t mA[8], mB[8];
            #pragma unroll
            for (int nf = 0; nf < 8; ++nf) {
                int col = colb + 8 * nf + 2 * tl;
                mA[nf] = *(const uint32_t*)(m0p + col);
                mB[nf] = *(const uint32_t*)(m1p + col);
            }

            // QK scores: Qh * Kh (already in log2 domain)
            float c[8][4];
            #pragma unroll
            for (int nf = 0; nf < 8; ++nf)
                #pragma unroll
                for (int i = 0; i < 4; ++i) c[nf][i] = 0.f;
            #pragma unroll
            for (int kc = 0; kc < 4; ++kc) {
                const uint32_t bcol = kc * 32 + (mi & 1) * 16;
                #pragma unroll
                for (int nf2 = 0; nf2 < 4; ++nf2) {
                    uint32_t bH[4];
                    uint32_t brow = (uint32_t)(co + nf2 * 16 + ((mi >> 1) << 3) + l7) * RB;
                    ldsm4(bH, bK + brow + bcol);
                    mma_f16(c[2 * nf2],     aQH[kc], bH[0], bH[1]);
                    mma_f16(c[2 * nf2 + 1], aQH[kc], bH[2], bH[3]);
                }
            }

            // e = ex2(s); pack fp16; mask multiply; store + PV A-frags
            uint32_t ph[4][4];
            #pragma unroll
            for (int nf = 0; nf < 8; ++nf) {
                int col = colb + 8 * nf + 2 * tl;
                float e0 = ex2f(c[nf][0]);
                float e1 = ex2f(c[nf][1]);
                float e2 = ex2f(c[nf][2]);
                float e3 = ex2f(c[nf][3]);
                uint32_t p01 = mul2(pack_h2(e0, e1), mA[nf]);
                uint32_t p23 = mul2(pack_h2(e2, e3), mB[nf]);
                *(uint32_t*)(e0p + col) = p01;
                *(uint32_t*)(e1p + col) = p23;
                ph[nf >> 1][((nf & 1) << 1) | 0] = p01;
                ph[nf >> 1][((nf & 1) << 1) | 1] = p23;
            }

            // PV: O += Ph * Vh
            #pragma unroll
            for (int kc = 0; kc < 4; ++kc) {
                uint32_t vrow = (uint32_t)(co + kc * 16 + ((mi & 1) << 3) + l7) * RB;
                #pragma unroll
                for (int db2 = 0; db2 < 4; ++db2) {
                    uint32_t vh[4];
                    ldsm4t(vh, bV + vrow + db2 * 32 + (mi >> 1) * 16);
                    mma_f16(o[2 * db2],     ph[kc], vh[0], vh[1]);
                    mma_f16(o[2 * db2 + 1], ph[kc], vh[2], vh[3]);
                }
            }
        }
    }

    // ---- O write (RAW, normalized later by k2) ----
    #pragma unroll
    for (int df = 0; df < 8; ++df) {
        int colc = 8 * df + 2 * tl;
        *(float2*)(Og + (size_t)r0 * D_ + colc) =
            make_float2(o[df][0], o[df][1]);
        *(float2*)(Og + (size_t)(r0 + 8) * D_ + colc) =
            make_float2(o[df][2], o[df][3]);
    }
}

// ---------- k2: warp-per-row rowsum + W = e*rinv + O normalize ----------
__global__ void __launch_bounds__(256, 8)
sdpa_norm(float* __restrict__ out, float* __restrict__ wts)
{
    const int w = threadIdx.x >> 5, lane = threadIdx.x & 31;
    const int row = blockIdx.x * 8 + w;              // 0 .. B*H*S-1

    const uint4* ep = (const uint4*)(g_e + (size_t)row * S_);   // 256 x 16B
    float4*      wp = (float4*)(wts + (size_t)row * S_);        // 512 x 16B

    // pass 1: load e (kept in regs), accumulate sum
    uint4 ev[8];
    float s = 0.f;
    #pragma unroll
    for (int j = 0; j < 8; ++j) {
        ev[j] = ep[j * 32 + lane];
        float2 a = __half22float2(*(const __half2*)&ev[j].x);
        float2 b = __half22float2(*(const __half2*)&ev[j].y);
        float2 c = __half22float2(*(const __half2*)&ev[j].z);
        float2 d = __half22float2(*(const __half2*)&ev[j].w);
        s += (a.x + a.y) + (b.x + b.y) + (c.x + c.y) + (d.x + d.y);
    }
    #pragma unroll
    for (int off = 16; off > 0; off >>= 1)
        s += __shfl_xor_sync(0xffffffffu, s, off);
    const float ri = 1.0f / s;

    // pass 2: W = e * rinv
    #pragma unroll
    for (int j = 0; j < 8; ++j) {
        float2 a = __half22float2(*(const __half2*)&ev[j].x);
        float2 b = __half22float2(*(const __half2*)&ev[j].y);
        float2 c = __half22float2(*(const __half2*)&ev[j].z);
        float2 d = __half22float2(*(const __half2*)&ev[j].w);
        int p = (j * 32 + lane) * 2;
        wp[p]     = make_float4(a.x * ri, a.y * ri, b.x * ri, b.y * ri);
        wp[p + 1] = make_float4(c.x * ri, c.y * ri, d.x * ri, d.y * ri);
    }

    // O row normalize (64 floats = 16 float4, lanes 0..15)
    if (lane < 16) {
        float4* op = (float4*)(out + (size_t)row * D_) + lane;
        float4 ov = *op;
        ov.x *= ri; ov.y *= ri; ov.z *= ri; ov.w *= ri;
        *op = ov;
    }
}

extern "C" void kernel_launch(void* const* d_in, const int* in_sizes, int n_in,
                              void* d_out, int out_size)
{
    const float* Q    = (const float*)d_in[0];
    const float* K    = (const float*)d_in[1];
    const float* V    = (const float*)d_in[2];
    const int*   mask = (const int*)d_in[3];

    float* out = (float*)d_out;
    float* wts = out + (size_t)B_ * H_ * S_ * D_;

    cudaFuncSetAttribute(sdpa_fused, cudaFuncAttributeMaxDynamicSharedMemorySize, SMEM_SZ);

    cvt_kv<<<(B_ * H_ * S_ * D_ / 4) / 256, 256>>>(K, V);
    cvt_mask<<<(B_ * S_ * S_ / 4) / 256, 256>>>(mask);
    dim3 grid(S_ / BM, B_ * H_);
    sdpa_fused<<<grid, NT, SMEM_SZ>>>(Q, out);
    sdpa_norm<<<B_ * H_ * S_ / 8, 256>>>(out, wts);
}

// round 15
// speedup vs baseline: 1.2382x; 1.2382x over previous
#include <cuda_runtime.h>
#include <cuda_fp16.h>
#include <cstdint>

// ScaledDotProductAttention B=4,H=16,S=2048,D=64 fp32 + mask [B,1,S,S] int32.
// out [B,H,S,D] then weights [B,H,S,S] concatenated in d_out.
//
// Round 14:
//   k0a (cvt_kv):   K,V f32 -> fp16 scratch.
//   k0b (cvt_mask): mask int32 -> fp16 {0,1} scratch.
//   k1  (sdpa_fused): cp.async double-buffered fp16 K/V; QK=Qh*Kh HMMA
//        (log2e folded into Q); e = ex2(s) -> fp16 -> mask HMUL2 -> g_e +
//        PV A-frags; PV=Ph*Vh; warp-local rowsum (from masked fp16 e) ->
//        g_rsum; O normalized in-warp, written once. No block reduction.
//   k2  (sdpa_rescale): block-per-row W = e(fp16)*rinv (measured 230us,
//        87% DRAM in round 11 -- no reduction, no sync).

#define B_ 4
#define H_ 16
#define S_ 2048
#define D_ 64

constexpr int BM = 128, BN = 128, NT = 256, NTILE = S_ / BN;
constexpr int RB = 144;                    // bytes per fp16 smem row (72 elems)

// double-buffered tile areas
constexpr int OFF_K0  = 0;
constexpr int OFF_V0  = 18432;
constexpr int OFF_K1  = 36864;
constexpr int OFF_V1  = 55296;
constexpr int SMEM_SZ = 73728;

__device__ float g_rsum[B_ * H_ * S_];
__device__ __align__(16) __half g_Kh[(size_t)B_ * H_ * S_ * D_];
__device__ __align__(16) __half g_Vh[(size_t)B_ * H_ * S_ * D_];
__device__ __align__(16) __half g_Mh[(size_t)B_ * S_ * S_];        // fp16 {0,1}
__device__ __align__(16) __half g_e[(size_t)B_ * H_ * S_ * S_];    // 536 MB scratch

// ---------- helpers ----------
__device__ __forceinline__ uint32_t smem_u32(const void* p) {
    uint32_t a;
    asm("{ .reg .u64 t; cvta.to.shared.u64 t, %1; cvt.u32.u64 %0, t; }" : "=r"(a) : "l"(p));
    return a;
}
__device__ __forceinline__ void ldsm4(uint32_t* r, uint32_t a) {
    asm volatile("ldmatrix.sync.aligned.m8n8.x4.shared.b16 {%0,%1,%2,%3}, [%4];"
                 : "=r"(r[0]), "=r"(r[1]), "=r"(r[2]), "=r"(r[3]) : "r"(a));
}
__device__ __forceinline__ void ldsm4t(uint32_t* r, uint32_t a) {
    asm volatile("ldmatrix.sync.aligned.m8n8.x4.trans.shared.b16 {%0,%1,%2,%3}, [%4];"
                 : "=r"(r[0]), "=r"(r[1]), "=r"(r[2]), "=r"(r[3]) : "r"(a));
}
__device__ __forceinline__ void mma_f16(float* c, const uint32_t* a, uint32_t b0, uint32_t b1) {
    asm volatile(
        "mma.sync.aligned.m16n8k16.row.col.f32.f16.f16.f32 "
        "{%0,%1,%2,%3}, {%4,%5,%6,%7}, {%8,%9}, {%0,%1,%2,%3};"
        : "+f"(c[0]), "+f"(c[1]), "+f"(c[2]), "+f"(c[3])
        : "r"(a[0]), "r"(a[1]), "r"(a[2]), "r"(a[3]), "r"(b0), "r"(b1));
}
__device__ __forceinline__ uint32_t pack_h2(float a, float b) {
    __half2 h = __floats2half2_rn(a, b);
    return *(uint32_t*)&h;
}
__device__ __forceinline__ uint32_t mul2(uint32_t a, uint32_t b) {
    __half2 r = __hmul2(*(__half2*)&a, *(__half2*)&b);
    return *(uint32_t*)&r;
}
__device__ __forceinline__ float ex2f(float x) {
    float r; asm("ex2.approx.f32 %0, %1;" : "=f"(r) : "f"(x)); return r;
}
__device__ __forceinline__ void cp16(uint32_t dst, const void* src) {
    asm volatile("cp.async.cg.shared.global [%0], [%1], 16;" :: "r"(dst), "l"(src));
}
#define CP_COMMIT() asm volatile("cp.async.commit_group;" ::: "memory")
#define CP_WAIT0()  asm volatile("cp.async.wait_group 0;" ::: "memory")

// ---------- k0a: K,V f32 -> fp16 scratch ----------
__global__ void __launch_bounds__(256, 8)
cvt_kv(const float* __restrict__ K, const float* __restrict__ V)
{
    int i = blockIdx.x * 256 + threadIdx.x;       // 0 .. B*H*S*D/4-1
    float4 a = ((const float4*)K)[i];
    ((uint2*)g_Kh)[i] = make_uint2(pack_h2(a.x, a.y), pack_h2(a.z, a.w));
    float4 b = ((const float4*)V)[i];
    ((uint2*)g_Vh)[i] = make_uint2(pack_h2(b.x, b.y), pack_h2(b.z, b.w));
}

// ---------- k0b: mask int32 -> fp16 {0,1} ----------
__global__ void __launch_bounds__(256, 8)
cvt_mask(const int* __restrict__ mask)
{
    int i = blockIdx.x * 256 + threadIdx.x;       // 0 .. B*S*S/4-1
    int4 m = ((const int4*)mask)[i];
    ((uint2*)g_Mh)[i] = make_uint2(pack_h2((float)m.x, (float)m.y),
                                   pack_h2((float)m.z, (float)m.w));
}

// ---------- k1: QK+ex2+mask -> e(fp16) to g_e, PV -> O, rowsums ----------
__global__ void __launch_bounds__(NT, 2)
sdpa_fused(const float* __restrict__ Q, float* __restrict__ out)
{
    extern __shared__ char sm[];
    const uint32_t sb = smem_u32(sm);
    const int tid = threadIdx.x, w = tid >> 5, lid = tid & 31;
    const int g = lid >> 2, tl = lid & 3, mi = lid >> 3, l7 = lid & 7;
    const int bh = blockIdx.y, b = bh >> 4, q0 = blockIdx.x * BM;

    const float* Qg  = Q + ((size_t)bh * S_ + q0) * D_;
    const char*  KgH = (const char*)(g_Kh + (size_t)bh * S_ * D_);
    const char*  VgH = (const char*)(g_Vh + (size_t)bh * S_ * D_);
    const __half* Mh = g_Mh + (size_t)b * S_ * S_;
    float*       Og  = out + ((size_t)bh * S_ + q0) * D_;
    __half*      Eg  = g_e + ((size_t)bh * S_ + q0) * S_;

    // prologue: Q * (0.125*log2e) fp16 -> smem buf K0, hoist Q frags to regs
    const float QS = 0.125f * 1.44269504f;
    for (int idx = tid; idx < BM * 16; idx += NT) {
        int r = idx >> 4, c4 = (idx & 15) * 4;
        float4 v = *(const float4*)(Qg + (size_t)r * D_ + c4);
        *(uint2*)(sm + OFF_K0 + r * RB + c4 * 2) =
            make_uint2(pack_h2(v.x * QS, v.y * QS),
                       pack_h2(v.z * QS, v.w * QS));
    }
    __syncthreads();

    uint32_t aQH[4][4];
    {
        uint32_t arow = (uint32_t)(16 * w + ((mi & 1) << 3) + l7) * RB;
        #pragma unroll
        for (int kc = 0; kc < 4; ++kc)
            ldsm4(aQH[kc], sb + OFF_K0 + arow + kc * 32 + (mi >> 1) * 16);
    }
    __syncthreads();   // Q frags read before cp.async overwrites K0

    const uint32_t offK[2] = {sb + OFF_K0, sb + OFF_K1};
    const uint32_t offV[2] = {sb + OFF_V0, sb + OFF_V1};

    // issue tile 0
    {
        #pragma unroll
        for (int j = 0; j < 4; ++j) {
            int c = tid + 256 * j, row = c >> 3, cc = c & 7;
            cp16(offK[0] + row * RB + cc * 16, KgH + row * 128 + cc * 16);
            cp16(offV[0] + row * RB + cc * 16, VgH + row * 128 + cc * 16);
        }
        CP_COMMIT();
    }

    const int r0 = 16 * w + g;
    const __half* m0p = Mh + (size_t)(q0 + r0) * S_;
    const __half* m1p = Mh + (size_t)(q0 + r0 + 8) * S_;
    __half* e0p = Eg + (size_t)r0 * S_;
    __half* e1p = Eg + (size_t)(r0 + 8) * S_;

    float rs0 = 0.f, rs1 = 0.f;
    float o[8][4];
    #pragma unroll
    for (int df = 0; df < 8; ++df)
        #pragma unroll
        for (int i = 0; i < 4; ++i) o[df][i] = 0.f;

    for (int t = 0; t < NTILE; ++t) {
        CP_WAIT0();
        __syncthreads();    // tile t ready; prev compute done (buffer reuse safe)

        if (t + 1 < NTILE) {
            const char* ks = KgH + (size_t)(t + 1) * BN * D_ * 2;
            const char* vs = VgH + (size_t)(t + 1) * BN * D_ * 2;
            const uint32_t dK = offK[(t + 1) & 1], dV = offV[(t + 1) & 1];
            #pragma unroll
            for (int j = 0; j < 4; ++j) {
                int c = tid + 256 * j, row = c >> 3, cc = c & 7;
                cp16(dK + row * RB + cc * 16, ks + row * 128 + cc * 16);
                cp16(dV + row * RB + cc * 16, vs + row * 128 + cc * 16);
            }
            CP_COMMIT();
        }

        const uint32_t bK = offK[t & 1], bV = offV[t & 1];

        #pragma unroll
        for (int ch2 = 0; ch2 < 2; ++ch2) {
            const int co = 64 * ch2;
            const int colb = t * BN + co;

            // hoist mask loads (fp16 pairs): in flight during QK MMAs
            uint32_t mA[8], mB[8];
            #pragma unroll
            for (int nf = 0; nf < 8; ++nf) {
                int col = colb + 8 * nf + 2 * tl;
                mA[nf] = *(const uint32_t*)(m0p + col);
                mB[nf] = *(const uint32_t*)(m1p + col);
            }

            // QK scores: Qh * Kh (log2 domain)
            float c[8][4];
            #pragma unroll
            for (int nf = 0; nf < 8; ++nf)
                #pragma unroll
                for (int i = 0; i < 4; ++i) c[nf][i] = 0.f;
            #pragma unroll
            for (int kc = 0; kc < 4; ++kc) {
                const uint32_t bcol = kc * 32 + (mi & 1) * 16;
                #pragma unroll
                for (int nf2 = 0; nf2 < 4; ++nf2) {
                    uint32_t bH[4];
                    uint32_t brow = (uint32_t)(co + nf2 * 16 + ((mi >> 1) << 3) + l7) * RB;
                    ldsm4(bH, bK + brow + bcol);
                    mma_f16(c[2 * nf2],     aQH[kc], bH[0], bH[1]);
                    mma_f16(c[2 * nf2 + 1], aQH[kc], bH[2], bH[3]);
                }
            }

            // e = ex2(s) -> fp16 -> mask; store; rowsum from masked fp16 e
            uint32_t ph[4][4];
            #pragma unroll
            for (int nf = 0; nf < 8; ++nf) {
                int col = colb + 8 * nf + 2 * tl;
                float e0 = ex2f(c[nf][0]);
                float e1 = ex2f(c[nf][1]);
                float e2 = ex2f(c[nf][2]);
                float e3 = ex2f(c[nf][3]);
                uint32_t p01 = mul2(pack_h2(e0, e1), mA[nf]);
                uint32_t p23 = mul2(pack_h2(e2, e3), mB[nf]);
                *(uint32_t*)(e0p + col) = p01;
                *(uint32_t*)(e1p + col) = p23;
                float2 f01 = __half22float2(*(__half2*)&p01);
                float2 f23 = __half22float2(*(__half2*)&p23);
                rs0 += f01.x + f01.y;
                rs1 += f23.x + f23.y;
                ph[nf >> 1][((nf & 1) << 1) | 0] = p01;
                ph[nf >> 1][((nf & 1) << 1) | 1] = p23;
            }

            // PV: O += Ph * Vh
            #pragma unroll
            for (int kc = 0; kc < 4; ++kc) {
                uint32_t vrow = (uint32_t)(co + kc * 16 + ((mi & 1) << 3) + l7) * RB;
                #pragma unroll
                for (int db2 = 0; db2 < 4; ++db2) {
                    uint32_t vh[4];
                    ldsm4t(vh, bV + vrow + db2 * 32 + (mi >> 1) * 16);
                    mma_f16(o[2 * db2],     ph[kc], vh[0], vh[1]);
                    mma_f16(o[2 * db2 + 1], ph[kc], vh[2], vh[3]);
                }
            }
        }
    }

    // ---- warp-local rowsum reduce (4 lanes per row) -> g_rsum ----
    rs0 += __shfl_xor_sync(0xffffffffu, rs0, 1);
    rs0 += __shfl_xor_sync(0xffffffffu, rs0, 2);
    rs1 += __shfl_xor_sync(0xffffffffu, rs1, 1);
    rs1 += __shfl_xor_sync(0xffffffffu, rs1, 2);
    if (tl == 0) {
        g_rsum[(size_t)bh * S_ + q0 + r0]     = rs0;
        g_rsum[(size_t)bh * S_ + q0 + r0 + 8] = rs1;
    }

    // ---- O write (normalized in-warp, no sync needed) ----
    const float ri0 = 1.0f / rs0, ri1 = 1.0f / rs1;
    #pragma unroll
    for (int df = 0; df < 8; ++df) {
        int colc = 8 * df + 2 * tl;
        *(float2*)(Og + (size_t)r0 * D_ + colc) =
            make_float2(o[df][0] * ri0, o[df][1] * ri0);
        *(float2*)(Og + (size_t)(r0 + 8) * D_ + colc) =
            make_float2(o[df][2] * ri1, o[df][3] * ri1);
    }
}

// ---------- k2: W = e(fp16) * rinv (one block per row; round-11 shape) ----------
__global__ void __launch_bounds__(256, 8)
sdpa_rescale(float* __restrict__ wts)
{
    const int row = blockIdx.x;                 // 0 .. B*H*S-1
    const float ri = 1.0f / g_rsum[row];
    const int tid = threadIdx.x;

    const uint4 ev = ((const uint4*)(g_e + (size_t)row * S_))[tid];
    float2 f0 = __half22float2(*(const __half2*)&ev.x);
    float2 f1 = __half22float2(*(const __half2*)&ev.y);
    float2 f2 = __half22float2(*(const __half2*)&ev.z);
    float2 f3 = __half22float2(*(const __half2*)&ev.w);

    float4* p = (float4*)(wts + (size_t)row * S_ + 8 * tid);
    p[0] = make_float4(f0.x * ri, f0.y * ri, f1.x * ri, f1.y * ri);
    p[1] = make_float4(f2.x * ri, f2.y * ri, f3.x * ri, f3.y * ri);
}

extern "C" void kernel_launch(void* const* d_in, const int* in_sizes, int n_in,
                              void* d_out, int out_size)
{
    const float* Q    = (const float*)d_in[0];
    const float* K    = (const float*)d_in[1];
    const float* V    = (const float*)d_in[2];
    const int*   mask = (const int*)d_in[3];

    float* out = (float*)d_out;
    float* wts = out + (size_t)B_ * H_ * S_ * D_;

    cudaFuncSetAttribute(sdpa_fused, cudaFuncAttributeMaxDynamicSharedMemorySize, SMEM_SZ);

    cvt_kv<<<(B_ * H_ * S_ * D_ / 4) / 256, 256>>>(K, V);
    cvt_mask<<<(B_ * S_ * S_ / 4) / 256, 256>>>(mask);
    dim3 grid(S_ / BM, B_ * H_);
    sdpa_fused<<<grid, NT, SMEM_SZ>>>(Q, out);
    sdpa_rescale<<<B_ * H_ * S_, 256>>>(wts);
}

// round 17
// speedup vs baseline: 1.2405x; 1.0019x over previous
#include <cuda_runtime.h>
#include <cuda_fp16.h>
#include <cstdint>

// ScaledDotProductAttention B=4,H=16,S=2048,D=64 fp32 + mask [B,1,S,S] int32.
// out [B,H,S,D] then weights [B,H,S,S] concatenated in d_out.
//
// Round 16 (= round 15 with the cvt grid bug fixed):
//   k0a (cvt_kv):   K,V f32 -> fp16 scratch   (grid covers B*H*S*D/4).
//   k0b (cvt_mask): mask int32 -> fp16 {0,1}  (grid covers B*S*S/4).
//   k1  (sdpa_fused): cp.async double-buffered fp16 K/V; QK=Qh*Kh HMMA
//        (log2e folded into Q); e = ex2(s) -> fp16 -> mask HMUL2 -> g_e (.cs) +
//        PV A-frags; PV=Ph*Vh; warp-local rowsum -> g_rsum; O normalized
//        in-warp. Mask via __ldg.
//   k2  (sdpa_rescale): 2 rows/block, __ldcs e + __stcs W (MLP=2, streaming).

#define B_ 4
#define H_ 16
#define S_ 2048
#define D_ 64

constexpr int BM = 128, BN = 128, NT = 256, NTILE = S_ / BN;
constexpr int RB = 144;                    // bytes per fp16 smem row (72 elems)

// double-buffered tile areas
constexpr int OFF_K0  = 0;
constexpr int OFF_V0  = 18432;
constexpr int OFF_K1  = 36864;
constexpr int OFF_V1  = 55296;
constexpr int SMEM_SZ = 73728;

__device__ float g_rsum[B_ * H_ * S_];
__device__ __align__(16) __half g_Kh[(size_t)B_ * H_ * S_ * D_];
__device__ __align__(16) __half g_Vh[(size_t)B_ * H_ * S_ * D_];
__device__ __align__(16) __half g_Mh[(size_t)B_ * S_ * S_];        // fp16 {0,1}
__device__ __align__(16) __half g_e[(size_t)B_ * H_ * S_ * S_];    // 536 MB scratch

// ---------- helpers ----------
__device__ __forceinline__ uint32_t smem_u32(const void* p) {
    uint32_t a;
    asm("{ .reg .u64 t; cvta.to.shared.u64 t, %1; cvt.u32.u64 %0, t; }" : "=r"(a) : "l"(p));
    return a;
}
__device__ __forceinline__ void ldsm4(uint32_t* r, uint32_t a) {
    asm volatile("ldmatrix.sync.aligned.m8n8.x4.shared.b16 {%0,%1,%2,%3}, [%4];"
                 : "=r"(r[0]), "=r"(r[1]), "=r"(r[2]), "=r"(r[3]) : "r"(a));
}
__device__ __forceinline__ void ldsm4t(uint32_t* r, uint32_t a) {
    asm volatile("ldmatrix.sync.aligned.m8n8.x4.trans.shared.b16 {%0,%1,%2,%3}, [%4];"
                 : "=r"(r[0]), "=r"(r[1]), "=r"(r[2]), "=r"(r[3]) : "r"(a));
}
__device__ __forceinline__ void mma_f16(float* c, const uint32_t* a, uint32_t b0, uint32_t b1) {
    asm volatile(
        "mma.sync.aligned.m16n8k16.row.col.f32.f16.f16.f32 "
        "{%0,%1,%2,%3}, {%4,%5,%6,%7}, {%8,%9}, {%0,%1,%2,%3};"
        : "+f"(c[0]), "+f"(c[1]), "+f"(c[2]), "+f"(c[3])
        : "r"(a[0]), "r"(a[1]), "r"(a[2]), "r"(a[3]), "r"(b0), "r"(b1));
}
__device__ __forceinline__ uint32_t pack_h2(float a, float b) {
    __half2 h = __floats2half2_rn(a, b);
    return *(uint32_t*)&h;
}
__device__ __forceinline__ uint32_t mul2(uint32_t a, uint32_t b) {
    __half2 r = __hmul2(*(__half2*)&a, *(__half2*)&b);
    return *(uint32_t*)&r;
}
__device__ __forceinline__ float ex2f(float x) {
    float r; asm("ex2.approx.f32 %0, %1;" : "=f"(r) : "f"(x)); return r;
}
__device__ __forceinline__ void cp16(uint32_t dst, const void* src) {
    asm volatile("cp.async.cg.shared.global [%0], [%1], 16;" :: "r"(dst), "l"(src));
}
__device__ __forceinline__ void stcs32(void* p, uint32_t v) {
    asm volatile("st.global.cs.b32 [%0], %1;" :: "l"(p), "r"(v) : "memory");
}
#define CP_COMMIT() asm volatile("cp.async.commit_group;" ::: "memory")
#define CP_WAIT0()  asm volatile("cp.async.wait_group 0;" ::: "memory")

// ---------- k0a: K,V f32 -> fp16 scratch ----------
__global__ void __launch_bounds__(256, 8)
cvt_kv(const float* __restrict__ K, const float* __restrict__ V)
{
    int i = blockIdx.x * 256 + threadIdx.x;       // 0 .. B*H*S*D/4-1
    float4 a = ((const float4*)K)[i];
    ((uint2*)g_Kh)[i] = make_uint2(pack_h2(a.x, a.y), pack_h2(a.z, a.w));
    float4 b = ((const float4*)V)[i];
    ((uint2*)g_Vh)[i] = make_uint2(pack_h2(b.x, b.y), pack_h2(b.z, b.w));
}

// ---------- k0b: mask int32 -> fp16 {0,1} ----------
__global__ void __launch_bounds__(256, 8)
cvt_mask(const int* __restrict__ mask)
{
    int i = blockIdx.x * 256 + threadIdx.x;       // 0 .. B*S*S/4-1
    int4 m = ((const int4*)mask)[i];
    ((uint2*)g_Mh)[i] = make_uint2(pack_h2((float)m.x, (float)m.y),
                                   pack_h2((float)m.z, (float)m.w));
}

// ---------- k1: QK+ex2+mask -> e(fp16) to g_e, PV -> O, rowsums ----------
__global__ void __launch_bounds__(NT, 2)
sdpa_fused(const float* __restrict__ Q, float* __restrict__ out)
{
    extern __shared__ char sm[];
    const uint32_t sb = smem_u32(sm);
    const int tid = threadIdx.x, w = tid >> 5, lid = tid & 31;
    const int g = lid >> 2, tl = lid & 3, mi = lid >> 3, l7 = lid & 7;
    const int bh = blockIdx.y, b = bh >> 4, q0 = blockIdx.x * BM;

    const float* Qg  = Q + ((size_t)bh * S_ + q0) * D_;
    const char*  KgH = (const char*)(g_Kh + (size_t)bh * S_ * D_);
    const char*  VgH = (const char*)(g_Vh + (size_t)bh * S_ * D_);
    const __half* Mh = g_Mh + (size_t)b * S_ * S_;
    float*       Og  = out + ((size_t)bh * S_ + q0) * D_;
    __half*      Eg  = g_e + ((size_t)bh * S_ + q0) * S_;

    // prologue: Q * (0.125*log2e) fp16 -> smem buf K0, hoist Q frags to regs
    const float QS = 0.125f * 1.44269504f;
    for (int idx = tid; idx < BM * 16; idx += NT) {
        int r = idx >> 4, c4 = (idx & 15) * 4;
        float4 v = *(const float4*)(Qg + (size_t)r * D_ + c4);
        *(uint2*)(sm + OFF_K0 + r * RB + c4 * 2) =
            make_uint2(pack_h2(v.x * QS, v.y * QS),
                       pack_h2(v.z * QS, v.w * QS));
    }
    __syncthreads();

    uint32_t aQH[4][4];
    {
        uint32_t arow = (uint32_t)(16 * w + ((mi & 1) << 3) + l7) * RB;
        #pragma unroll
        for (int kc = 0; kc < 4; ++kc)
            ldsm4(aQH[kc], sb + OFF_K0 + arow + kc * 32 + (mi >> 1) * 16);
    }
    __syncthreads();   // Q frags read before cp.async overwrites K0

    const uint32_t offK[2] = {sb + OFF_K0, sb + OFF_K1};
    const uint32_t offV[2] = {sb + OFF_V0, sb + OFF_V1};

    // issue tile 0
    {
        #pragma unroll
        for (int j = 0; j < 4; ++j) {
            int c = tid + 256 * j, row = c >> 3, cc = c & 7;
            cp16(offK[0] + row * RB + cc * 16, KgH + row * 128 + cc * 16);
            cp16(offV[0] + row * RB + cc * 16, VgH + row * 128 + cc * 16);
        }
        CP_COMMIT();
    }

    const int r0 = 16 * w + g;
    const __half* m0p = Mh + (size_t)(q0 + r0) * S_;
    const __half* m1p = Mh + (size_t)(q0 + r0 + 8) * S_;
    __half* e0p = Eg + (size_t)r0 * S_;
    __half* e1p = Eg + (size_t)(r0 + 8) * S_;

    float rs0 = 0.f, rs1 = 0.f;
    float o[8][4];
    #pragma unroll
    for (int df = 0; df < 8; ++df)
        #pragma unroll
        for (int i = 0; i < 4; ++i) o[df][i] = 0.f;

    for (int t = 0; t < NTILE; ++t) {
        CP_WAIT0();
        __syncthreads();    // tile t ready; prev compute done (buffer reuse safe)

        if (t + 1 < NTILE) {
            const char* ks = KgH + (size_t)(t + 1) * BN * D_ * 2;
            const char* vs = VgH + (size_t)(t + 1) * BN * D_ * 2;
            const uint32_t dK = offK[(t + 1) & 1], dV = offV[(t + 1) & 1];
            #pragma unroll
            for (int j = 0; j < 4; ++j) {
                int c = tid + 256 * j, row = c >> 3, cc = c & 7;
                cp16(dK + row * RB + cc * 16, ks + row * 128 + cc * 16);
                cp16(dV + row * RB + cc * 16, vs + row * 128 + cc * 16);
            }
            CP_COMMIT();
        }

        const uint32_t bK = offK[t & 1], bV = offV[t & 1];

        #pragma unroll
        for (int ch2 = 0; ch2 < 2; ++ch2) {
            const int co = 64 * ch2;
            const int colb = t * BN + co;

            // hoist mask loads (fp16 pairs, nc path): in flight during QK MMAs
            uint32_t mA[8], mB[8];
            #pragma unroll
            for (int nf = 0; nf < 8; ++nf) {
                int col = colb + 8 * nf + 2 * tl;
                mA[nf] = __ldg((const uint32_t*)(m0p + col));
                mB[nf] = __ldg((const uint32_t*)(m1p + col));
            }

            // QK scores: Qh * Kh (log2 domain)
            float c[8][4];
            #pragma unroll
            for (int nf = 0; nf < 8; ++nf)
                #pragma unroll
                for (int i = 0; i < 4; ++i) c[nf][i] = 0.f;
            #pragma unroll
            for (int kc = 0; kc < 4; ++kc) {
                const uint32_t bcol = kc * 32 + (mi & 1) * 16;
                #pragma unroll
                for (int nf2 = 0; nf2 < 4; ++nf2) {
                    uint32_t bH[4];
                    uint32_t brow = (uint32_t)(co + nf2 * 16 + ((mi >> 1) << 3) + l7) * RB;
                    ldsm4(bH, bK + brow + bcol);
                    mma_f16(c[2 * nf2],     aQH[kc], bH[0], bH[1]);
                    mma_f16(c[2 * nf2 + 1], aQH[kc], bH[2], bH[3]);
                }
            }

            // e = ex2(s) -> fp16 -> mask; store .cs; rowsum from masked fp16 e
            uint32_t ph[4][4];
            #pragma unroll
            for (int nf = 0; nf < 8; ++nf) {
                int col = colb + 8 * nf + 2 * tl;
                float e0 = ex2f(c[nf][0]);
                float e1 = ex2f(c[nf][1]);
                float e2 = ex2f(c[nf][2]);
                float e3 = ex2f(c[nf][3]);
                uint32_t p01 = mul2(pack_h2(e0, e1), mA[nf]);
                uint32_t p23 = mul2(pack_h2(e2, e3), mB[nf]);
                stcs32(e0p + col, p01);
                stcs32(e1p + col, p23);
                float2 f01 = __half22float2(*(__half2*)&p01);
                float2 f23 = __half22float2(*(__half2*)&p23);
                rs0 += f01.x + f01.y;
                rs1 += f23.x + f23.y;
                ph[nf >> 1][((nf & 1) << 1) | 0] = p01;
                ph[nf >> 1][((nf & 1) << 1) | 1] = p23;
            }

            // PV: O += Ph * Vh
            #pragma unroll
            for (int kc = 0; kc < 4; ++kc) {
                uint32_t vrow = (uint32_t)(co + kc * 16 + ((mi & 1) << 3) + l7) * RB;
                #pragma unroll
                for (int db2 = 0; db2 < 4; ++db2) {
                    uint32_t vh[4];
                    ldsm4t(vh, bV + vrow + db2 * 32 + (mi >> 1) * 16);
                    mma_f16(o[2 * db2],     ph[kc], vh[0], vh[1]);
                    mma_f16(o[2 * db2 + 1], ph[kc], vh[2], vh[3]);
                }
            }
        }
    }

    // ---- warp-local rowsum reduce (4 lanes per row) -> g_rsum ----
    rs0 += __shfl_xor_sync(0xffffffffu, rs0, 1);
    rs0 += __shfl_xor_sync(0xffffffffu, rs0, 2);
    rs1 += __shfl_xor_sync(0xffffffffu, rs1, 1);
    rs1 += __shfl_xor_sync(0xffffffffu, rs1, 2);
    if (tl == 0) {
        g_rsum[(size_t)bh * S_ + q0 + r0]     = rs0;
        g_rsum[(size_t)bh * S_ + q0 + r0 + 8] = rs1;
    }

    // ---- O write (normalized in-warp, no sync needed) ----
    const float ri0 = 1.0f / rs0, ri1 = 1.0f / rs1;
    #pragma unroll
    for (int df = 0; df < 8; ++df) {
        int colc = 8 * df + 2 * tl;
        *(float2*)(Og + (size_t)r0 * D_ + colc) =
            make_float2(o[df][0] * ri0, o[df][1] * ri0);
        *(float2*)(Og + (size_t)(r0 + 8) * D_ + colc) =
            make_float2(o[df][2] * ri1, o[df][3] * ri1);
    }
}

// ---------- k2: W = e(fp16) * rinv, 2 rows/block, streaming ----------
__global__ void __launch_bounds__(256, 8)
sdpa_rescale(float* __restrict__ wts)
{
    const int row = blockIdx.x * 2;             // 0 .. B*H*S-1 (step 2)
    const int tid = threadIdx.x;
    const float ri0 = 1.0f / g_rsum[row];
    const float ri1 = 1.0f / g_rsum[row + 1];

    // two independent 16B e loads in flight (MLP=2), streaming policy
    const uint4 ea = __ldcs(((const uint4*)(g_e + (size_t)row * S_)) + tid);
    const uint4 eb = __ldcs(((const uint4*)(g_e + (size_t)(row + 1) * S_)) + tid);

    float2 a0 = __half22float2(*(const __half2*)&ea.x);
    float2 a1 = __half22float2(*(const __half2*)&ea.y);
    float2 a2 = __half22float2(*(const __half2*)&ea.z);
    float2 a3 = __half22float2(*(const __half2*)&ea.w);
    float4* pa = (float4*)(wts + (size_t)row * S_ + 8 * tid);
    __stcs(pa,     make_float4(a0.x * ri0, a0.y * ri0, a1.x * ri0, a1.y * ri0));
    __stcs(pa + 1, make_float4(a2.x * ri0, a2.y * ri0, a3.x * ri0, a3.y * ri0));

    float2 b0 = __half22float2(*(const __half2*)&eb.x);
    float2 b1 = __half22float2(*(const __half2*)&eb.y);
    float2 b2 = __half22float2(*(const __half2*)&eb.z);
    float2 b3 = __half22float2(*(const __half2*)&eb.w);
    float4* pb = (float4*)(wts + (size_t)(row + 1) * S_ + 8 * tid);
    __stcs(pb,     make_float4(b0.x * ri1, b0.y * ri1, b1.x * ri1, b1.y * ri1));
    __stcs(pb + 1, make_float4(b2.x * ri1, b2.y * ri1, b3.x * ri1, b3.y * ri1));
}

extern "C" void kernel_launch(void* const* d_in, const int* in_sizes, int n_in,
                              void* d_out, int out_size)
{
    const float* Q    = (const float*)d_in[0];
    const float* K    = (const float*)d_in[1];
    const float* V    = (const float*)d_in[2];
    const int*   mask = (const int*)d_in[3];

    float* out = (float*)d_out;
    float* wts = out + (size_t)B_ * H_ * S_ * D_;

    cudaFuncSetAttribute(sdpa_fused, cudaFuncAttributeMaxDynamicSharedMemorySize, SMEM_SZ);

    cvt_kv<<<(B_ * H_ * S_ * D_ / 4) / 256, 256>>>(K, V);
    cvt_mask<<<(B_ * S_ * S_ / 4) / 256, 256>>>(mask);
    dim3 grid(S_ / BM, B_ * H_);
    sdpa_fused<<<grid, NT, SMEM_SZ>>>(Q, out);
    sdpa_rescale<<<B_ * H_ * S_ / 2, 256>>>(wts);
}